// round 4
// baseline (speedup 1.0000x reference)
#include <cuda_runtime.h>
#include <cuda_bf16.h>

// ---------------------------------------------------------------------------
// QuantWeightNet forward, k-packed f32x2 formulation, 4 rows/thread.
//   out = sigmoid(relu(relu(relu(x@W1q.T+b1)@W2q.T+b2)@W4q.T+b4)@W3q.T)*0.8+0.1
//   Wq = per-tensor symmetric 3-bit quant: s = max|W|/3; q=clip(rint(W/s),-3,3)*s
//
// Packing: f32x2 lanes hold (even-k, odd-k) partial sums; weights stored dense
// as (w[2k], w[2k+1]) pairs; horizontal add finalizes each neuron. No weight
// duplication, no x duplication -> minimal LDS instruction count (the R3
// bottleneck: L1tex 95%, 4 cyc per broadcast LDS.128).
// ---------------------------------------------------------------------------

#define N_FEAT 64

// ull-unit offsets into the packed weight buffer (16B alignment: even indices)
#define OFF_W1  0     // [7][32]  (w1[j][2k],w1[j][2k+1])            224
#define OFF_BP1 224   // [7]      (b1[j], 0)                          7
#define OFF_W2  232   // [20][4]  jj<3:(w2[i][2jj],w2[i][2jj+1]) jj=3:(w2[i][6],b2[i])  80
#define OFF_W4  312   // [20][10] (w4[i][2j],w4[i][2j+1])            200
#define OFF_BP4 512   // [20]     (b4[i], 0)                          20
#define OFF_W3  532   // [10]     (w3[2j],w3[2j+1])                   10
#define NW      544   // padded

__device__ unsigned long long g_w[NW];

// ---- f32x2 helpers ----
__device__ __forceinline__ unsigned long long pk2(float lo, float hi) {
    unsigned long long r;
    asm("mov.b64 %0, {%1, %2};" : "=l"(r) : "f"(lo), "f"(hi));
    return r;
}
__device__ __forceinline__ void upk2(unsigned long long v, float& lo, float& hi) {
    asm("mov.b64 {%0, %1}, %2;" : "=f"(lo), "=f"(hi) : "l"(v));
}
__device__ __forceinline__ unsigned long long ffma2(unsigned long long a,
                                                    unsigned long long b,
                                                    unsigned long long c) {
    unsigned long long d;
    asm("fma.rn.f32x2 %0, %1, %2, %3;" : "=l"(d) : "l"(a), "l"(b), "l"(c));
    return d;
}
__device__ __forceinline__ unsigned long long mul2(unsigned long long a,
                                                   unsigned long long b) {
    unsigned long long d;
    asm("mul.rn.f32x2 %0, %1, %2;" : "=l"(d) : "l"(a), "l"(b));
    return d;
}
__device__ __forceinline__ float hadd2(unsigned long long v) {
    float lo, hi;
    upk2(v, lo, hi);
    return lo + hi;
}

// ---- prep: quantize + repack weights once per launch ----
__device__ __forceinline__ float block_maxabs(const float* w, int n, float* red, int t) {
    float m = 0.0f;
    for (int i = t; i < n; i += 256) m = fmaxf(m, fabsf(w[i]));
    red[t] = m;
    __syncthreads();
    for (int s = 128; s > 0; s >>= 1) {
        if (t < s) red[t] = fmaxf(red[t], red[t + s]);
        __syncthreads();
    }
    float r = red[0];
    __syncthreads();
    return r;
}
__device__ __forceinline__ float qv(float w, float s) {
    float q = rintf(w / s);              // round-half-even == jnp.round
    q = fminf(fmaxf(q, -3.0f), 3.0f);
    return q * s;
}

__global__ void prep_kernel(const float* __restrict__ W1, const float* __restrict__ b1,
                            const float* __restrict__ W2, const float* __restrict__ b2,
                            const float* __restrict__ W4, const float* __restrict__ b4,
                            const float* __restrict__ W3) {
    __shared__ float red[256];
    int t = threadIdx.x;
    float s1 = block_maxabs(W1, 7 * 64, red, t)  * (1.0f / 3.0f);
    float s2 = block_maxabs(W2, 20 * 7, red, t)  * (1.0f / 3.0f);
    float s4 = block_maxabs(W4, 20 * 20, red, t) * (1.0f / 3.0f);
    float s3 = block_maxabs(W3, 20, red, t)      * (1.0f / 3.0f);

    for (int i = t; i < 224; i += 256) {          // W1 k-pairs
        int j = i >> 5, kp = i & 31;
        g_w[OFF_W1 + i] = pk2(qv(W1[j * 64 + 2 * kp], s1), qv(W1[j * 64 + 2 * kp + 1], s1));
    }
    for (int i = t; i < 7; i += 256)              // fc1 bias init (b,0)
        g_w[OFF_BP1 + i] = pk2(b1[i], 0.0f);
    for (int i = t; i < 80; i += 256) {           // W2 k-pairs + bias augmentation
        int r = i >> 2, jj = i & 3;
        unsigned long long v;
        if (jj < 3) v = pk2(qv(W2[r * 7 + 2 * jj], s2), qv(W2[r * 7 + 2 * jj + 1], s2));
        else        v = pk2(qv(W2[r * 7 + 6], s2), b2[r]);   // pairs with (h6, 1.0)
        g_w[OFF_W2 + i] = v;
    }
    for (int i = t; i < 200; i += 256) {          // W4 k-pairs
        int r = i / 10, jp = i % 10;
        g_w[OFF_W4 + i] = pk2(qv(W4[r * 20 + 2 * jp], s4), qv(W4[r * 20 + 2 * jp + 1], s4));
    }
    for (int i = t; i < 20; i += 256)             // fc4 bias init (b,0)
        g_w[OFF_BP4 + i] = pk2(b4[i], 0.0f);
    for (int i = t; i < 10; i += 256)             // W3 k-pairs
        g_w[OFF_W3 + i] = pk2(qv(W3[2 * i], s3), qv(W3[2 * i + 1], s3));
}

// ---- main: 4 rows/thread, k-packed ----
__global__ __launch_bounds__(256, 2)
void mlp_kernel(const float* __restrict__ x, float* __restrict__ out,
                long long nQuads, long long B) {
    __shared__ __align__(16) unsigned long long sw[NW];
    for (int i = threadIdx.x; i < NW; i += 256) sw[i] = g_w[i];
    __syncthreads();

    long long gt = (long long)blockIdx.x * 256 + threadIdx.x;
    if (gt >= nQuads) return;
    long long row0 = gt * 4;

    // clamped row indices (tail safety; full quads resolve to row0+r)
    long long ri[4];
#pragma unroll
    for (int r = 0; r < 4; r++) {
        long long v = row0 + r;
        ri[r] = (v < B) ? v : (B - 1);
    }
    const float4* xp[4];
#pragma unroll
    for (int r = 0; r < 4; r++)
        xp[r] = reinterpret_cast<const float4*>(x + ri[r] * N_FEAT);

    // ================= fc1: 64 -> 7 (k-packed, bias in acc init) =============
    unsigned long long acc[4][7];
#pragma unroll
    for (int j = 0; j < 7; j++) {
        unsigned long long b = sw[OFF_BP1 + j];
#pragma unroll
        for (int r = 0; r < 4; r++) acc[r][j] = b;
    }

#pragma unroll
    for (int c = 0; c < 16; c++) {
        unsigned long long xq[4][2];
#pragma unroll
        for (int r = 0; r < 4; r++) {
            float4 v = __ldcs(&xp[r][c]);
            xq[r][0] = pk2(v.x, v.y);
            xq[r][1] = pk2(v.z, v.w);
        }
#pragma unroll
        for (int j = 0; j < 7; j++) {
            ulonglong2 w = *reinterpret_cast<const ulonglong2*>(&sw[OFF_W1 + j * 32 + 2 * c]);
#pragma unroll
            for (int r = 0; r < 4; r++) {
                acc[r][j] = ffma2(xq[r][0], w.x, acc[r][j]);
                acc[r][j] = ffma2(xq[r][1], w.y, acc[r][j]);
            }
        }
    }

    // h1 scalars -> packed pairs, augmented with 1.0 for fc2 bias
    unsigned long long h1p[4][4];
#pragma unroll
    for (int r = 0; r < 4; r++) {
        float h[7];
#pragma unroll
        for (int j = 0; j < 7; j++) h[j] = fmaxf(hadd2(acc[r][j]), 0.0f);
        h1p[r][0] = pk2(h[0], h[1]);
        h1p[r][1] = pk2(h[2], h[3]);
        h1p[r][2] = pk2(h[4], h[5]);
        h1p[r][3] = pk2(h[6], 1.0f);   // 1.0 multiplies b2 in augmented weight
    }

    // ================= fc2: 7 -> 20, two 2-row halves (register pressure) ====
    unsigned long long h2p[4][10];
#pragma unroll
    for (int half = 0; half < 2; half++) {
        float prev[2];
#pragma unroll
        for (int i = 0; i < 20; i++) {
            ulonglong2 wA = *reinterpret_cast<const ulonglong2*>(&sw[OFF_W2 + i * 4]);
            ulonglong2 wB = *reinterpret_cast<const ulonglong2*>(&sw[OFF_W2 + i * 4 + 2]);
#pragma unroll
            for (int rr = 0; rr < 2; rr++) {
                int r = half * 2 + rr;
                unsigned long long a = mul2(h1p[r][0], wA.x);
                a = ffma2(h1p[r][1], wA.y, a);
                a = ffma2(h1p[r][2], wB.x, a);
                a = ffma2(h1p[r][3], wB.y, a);   // includes h6*w6 + b2
                float v = fmaxf(hadd2(a), 0.0f);
                if (i & 1) h2p[r][i >> 1] = pk2(prev[rr], v);
                else       prev[rr] = v;
            }
        }
    }

    // ================= fc4: 20 -> 20 fused with fc3: 20 -> 1 =================
    unsigned long long o3[4];
#pragma unroll
    for (int r = 0; r < 4; r++) o3[r] = pk2(0.0f, 0.0f);
    float h3prev[4];

#pragma unroll
    for (int i = 0; i < 20; i++) {
        unsigned long long bi = sw[OFF_BP4 + i];
        unsigned long long a[4];
#pragma unroll
        for (int r = 0; r < 4; r++) a[r] = bi;
#pragma unroll
        for (int jp = 0; jp < 5; jp++) {
            ulonglong2 w = *reinterpret_cast<const ulonglong2*>(&sw[OFF_W4 + i * 10 + 2 * jp]);
#pragma unroll
            for (int r = 0; r < 4; r++) {
                a[r] = ffma2(h2p[r][2 * jp],     w.x, a[r]);
                a[r] = ffma2(h2p[r][2 * jp + 1], w.y, a[r]);
            }
        }
        if (i & 1) {
            unsigned long long w3 = sw[OFF_W3 + (i >> 1)];
#pragma unroll
            for (int r = 0; r < 4; r++) {
                float v = fmaxf(hadd2(a[r]), 0.0f);
                o3[r] = ffma2(pk2(h3prev[r], v), w3, o3[r]);   // h3 consumed on the fly
            }
        } else {
#pragma unroll
            for (int r = 0; r < 4; r++) h3prev[r] = fmaxf(hadd2(a[r]), 0.0f);
        }
    }

    // ================= sigmoid epilogue + store ===============================
    float o[4];
#pragma unroll
    for (int r = 0; r < 4; r++) {
        float z = hadd2(o3[r]);
        o[r] = 0.8f / (1.0f + __expf(-z)) + 0.1f;
    }

    if (row0 + 4 <= B) {
        __stcs(reinterpret_cast<float4*>(out + row0), make_float4(o[0], o[1], o[2], o[3]));
    } else {
#pragma unroll
        for (int r = 0; r < 4; r++)
            if (row0 + r < B) out[row0 + r] = o[r];
    }
}

extern "C" void kernel_launch(void* const* d_in, const int* in_sizes, int n_in,
                              void* d_out, int out_size) {
    const float* x  = (const float*)d_in[0];
    const float* W1 = (const float*)d_in[1];
    const float* b1 = (const float*)d_in[2];
    const float* W2 = (const float*)d_in[3];
    const float* b2 = (const float*)d_in[4];
    const float* W4 = (const float*)d_in[5];
    const float* b4 = (const float*)d_in[6];
    const float* W3 = (const float*)d_in[7];
    float* out = (float*)d_out;

    long long B = in_sizes[0] / N_FEAT;          // 4,000,000
    long long nQuads = (B + 3) / 4;              // 1,000,000
    int grid = (int)((nQuads + 255) / 256);

    prep_kernel<<<1, 256>>>(W1, b1, W2, b2, W4, b4, W3);
    mlp_kernel<<<grid, 256>>>(x, out, nQuads, B);
}